// round 12
// baseline (speedup 1.0000x reference)
#include <cuda_runtime.h>
#include <math_constants.h>
#include <cstdint>

// B=8, U=V=13 (UV=169), H=128, W=160 (HW=20480), TRUNC=4, disp -6..6
#define UV 169
#define VD 13
#define HW 20480
#define PIX 20                    // pixels per chunk; HW/PIX = 1024 = 2^10
#define NT 160                    // 8 threads per pixel, 5 warps
#define RS 20                     // smem row stride; RS%8==4 -> pass A banks bijective
#define BUF (UV * RS)             // 3380 floats per buffer
#define GUARD (5 * RS)            // 100 floats each side (pass B row overhang <= 4 rows)
#define SMEM_FLOATS (2 * GUARD + 2 * BUF)   // 6960
#define SMEM_BYTES (SMEM_FLOATS * 4)        // 27840 B -> 8 CTAs/SM
#define CHB 1024                  // chunks per batch (power of two!)
#define NCHUNKS (8 * CHB)         // 8192
#define L2E 1.4426950408889634f
#define NEGBIG (-1e30f)

__device__ __forceinline__ void cp_async16(unsigned int dst, const float* src) {
    asm volatile("cp.async.cg.shared.global [%0], [%1], 16;" :: "r"(dst), "l"(src) : "memory");
}
__device__ __forceinline__ void cp_commit() {
    asm volatile("cp.async.commit_group;" ::: "memory");
}
template<int N>
__device__ __forceinline__ void cp_wait() {
    asm volatile("cp.async.wait_group %0;" :: "n"(N) : "memory");
}
__device__ __forceinline__ float ex2f(float t) {
    float r;
    asm("ex2.approx.f32 %0, %1;" : "=f"(r) : "f"(t));
    return r;
}

__global__ __launch_bounds__(NT)
void flow_regression_kernel(const float* __restrict__ x, float* __restrict__ out) {
    extern __shared__ float s_raw[];
    float* s0 = s_raw + GUARD;            // buffer 0; buffer nb at s0 + nb*BUF
    const int tid = threadIdx.x;
    const int bid = blockIdx.x;
    const int G   = gridDim.x;
    const unsigned int sbase0 = (unsigned int)__cvta_generic_to_shared(s0);

    const int sub = tid & 7;              // eighth of per-pixel work
    const int p   = tid >> 3;             // pixel 0..19

    // load mapping: 845 16B lines (169 planes x 5). line tid: plane=tid/5, q=tid%5.
    // stepping by 160 lines advances exactly 32 planes (q fixed).
    const int plane0 = tid / 5;
    const int q0     = (tid - plane0 * 5) * 4;

    auto issue_load = [&](int g, int nb) {
        int b  = g >> 10;
        int ch = g & (CHB - 1);
        const float* gp = x + (size_t)b * (UV * HW) + ch * PIX + plane0 * HW + q0;
        unsigned int dst = sbase0 + (unsigned int)(nb * BUF + plane0 * RS + q0) * 4u;
        #pragma unroll
        for (int k = 0; k < 5; k++) {     // lines tid + 160k (800 lines)
            cp_async16(dst, gp);
            gp  += 32 * HW;
            dst += 32 * RS * 4;
        }
        if (tid < 45) cp_async16(dst, gp);   // lines 800..844 (planes 160..168)
        cp_commit();
    };

    issue_load(bid, 0);
    int nb = 0;

    for (int g = bid; g < NCHUNKS; g += G) {
        cp_wait<0>();
        __syncthreads();                  // buffer nb visible; reads of nb^1 finished
        if (g + G < NCHUNKS) issue_load(g + G, nb ^ 1);   // overlaps compute below

        const float* sp = s0 + nb * BUF + p;

        // ---- Pass A: argmax over 169, 8-way split, 4 independent chains ----
        float m0 = -CUDART_INF_F, m1 = -CUDART_INF_F, m2 = -CUDART_INF_F, m3 = -CUDART_INF_F;
        int   a0 = 0, a1 = 0, a2 = 0, a3 = 0;
        {
            const float* r = sp + sub * RS;
            #pragma unroll
            for (int t = 0; t < 21; t++) {
                float v = r[t * 8 * RS];
                int uv = sub + 8 * t;
                switch (t & 3) {
                    case 0: if (v > m0) { m0 = v; a0 = uv; } break;
                    case 1: if (v > m1) { m1 = v; a1 = uv; } break;
                    case 2: if (v > m2) { m2 = v; a2 = uv; } break;
                    default: if (v > m3) { m3 = v; a3 = uv; } break;
                }
            }
            if (sub == 0) {               // uv = 168 -> chain 1 (any chain; comparator absolute)
                float v = sp[168 * RS];
                if (v > m1) { m1 = v; a1 = 168; }
            }
        }
        // merge chains (first-occurrence: on tie keep lower uv)
        if (m2 > m0 || (m2 == m0 && a2 < a0)) { m0 = m2; a0 = a2; }
        if (m3 > m1 || (m3 == m1 && a3 < a1)) { m1 = m3; a1 = a3; }
        if (m1 > m0 || (m1 == m0 && a1 < a0)) { m0 = m1; a0 = a1; }
        float m = m0; int am = a0;

        #pragma unroll
        for (int off = 1; off <= 4; off <<= 1) {
            float mo = __shfl_xor_sync(0xffffffffu, m,  off);
            int   ao = __shfl_xor_sync(0xffffffffu, am, off);
            if (mo > m || (mo == m && ao < am)) { m = mo; am = ao; }
        }
        const int ui = am / VD;
        const int vi = am - ui * VD;
        const float cc = m * L2E;         // exp(x-m) = ex2(x*L2E - cc)

        // ---- Pass B (row-based): thread owns row du=sub-4; row du=+4 distributed ----
        unsigned int vmV = 0x1FFu;        // v = vi-4+j valid iff 0<=v<=12
        if (vi < 4) vmV &= (0x1FFu << (4 - vi));
        if (vi > 8) vmV &= (0x1FFu >> (vi - 8));

        const int u   = ui + sub - 4;
        const bool oku = (unsigned)u <= 12u;
        const int uc  = min(max(u, 0), 12);
        const float wu = (float)(u - 6);
        const unsigned int vm = oku ? vmV : 0u;

        float Zb = 0.0f, Zx = 0.0f, T = 0.0f;   // T = sum e*j
        {
            const float* r = sp + (uc * VD + vi - 4) * RS;  // guards absorb overhang
            #pragma unroll
            for (int j = 0; j < 9; j++) {
                float a = (vm & (1u << j)) ? r[j * RS] : NEGBIG;
                float e = ex2f(fmaf(a, L2E, -cc));
                Zb += e;
                T = fmaf(e, (float)j, T);
            }
        }
        const int u4 = ui + 4;
        const bool ok4 = (u4 <= 12);
        const int uc4 = min(u4, 12);
        const float wu4 = (float)(u4 - 6);
        {
            const float* r4 = sp + (uc4 * VD + vi - 4) * RS;
            bool oke = ok4 && ((vmV >> sub) & 1u);
            float a1e = oke ? r4[sub * RS] : NEGBIG;
            float e1 = ex2f(fmaf(a1e, L2E, -cc));
            Zx += e1;
            T = fmaf(e1, (float)sub, T);

            bool oke8 = ok4 && (sub == 0) && ((vmV >> 8) & 1u);
            float a2e = oke8 ? r4[8 * RS] : NEGBIG;
            float e2 = ex2f(fmaf(a2e, L2E, -cc));
            Zx += e2;
            T = fmaf(e2, 8.0f, T);
        }

        float Z  = Zb + Zx;
        float sU = fmaf(wu, Zb, wu4 * Zx);
        #pragma unroll
        for (int off = 1; off <= 4; off <<= 1) {
            Z  += __shfl_xor_sync(0xffffffffu, Z,  off);
            sU += __shfl_xor_sync(0xffffffffu, sU, off);
            T  += __shfl_xor_sync(0xffffffffu, T,  off);
        }

        if (sub == 0) {
            const int b  = g >> 10;
            const int ch = g & (CHB - 1);
            const float inv = __frcp_rn(Z);
            const float sV = fmaf((float)(vi - 10), Z, T);   // wv = (vi-10)+j
            const int pix = ch * PIX + p;
            out[(b * 2 + 0) * HW + pix] = sU * inv;
            out[(b * 2 + 1) * HW + pix] = sV * inv;
        }
        nb ^= 1;
        // next iteration's __syncthreads orders these reads before refill
    }
}

extern "C" void kernel_launch(void* const* d_in, const int* in_sizes, int n_in,
                              void* d_out, int out_size) {
    (void)in_sizes; (void)n_in; (void)out_size;
    const float* x = (const float*)d_in[0];
    float* out = (float*)d_out;

    static int nsm = 0;
    if (nsm == 0) {
        cudaDeviceGetAttribute(&nsm, cudaDevAttrMultiProcessorCount, 0);
        if (nsm <= 0) nsm = 148;
        cudaFuncSetAttribute(flow_regression_kernel,
                             cudaFuncAttributeMaxDynamicSharedMemorySize, SMEM_BYTES);
        cudaFuncSetAttribute(flow_regression_kernel,
                             cudaFuncAttributePreferredSharedMemoryCarveout, 100);
    }

    const int nblocks = 8 * nsm;      // persistent: 8 CTAs per SM
    flow_regression_kernel<<<nblocks, NT, SMEM_BYTES>>>(x, out);
}

// round 13
// speedup vs baseline: 1.1509x; 1.1509x over previous
#include <cuda_runtime.h>
#include <math_constants.h>
#include <cstdint>

// B=8, U=V=13 (UV=169), H=128, W=160 (HW=20480), TRUNC=4, disp -6..6
#define UV 169
#define VD 13
#define HW 20480
#define PIX 32                    // pixels per chunk (128B per plane -> full sectors)
#define NT 256                    // 8 threads per pixel
#define RS 36                     // smem row stride; pass A bank (4*sub+p) bijective
#define BUF (UV * RS)             // 6084 floats per buffer
#define GUARD 144                 // guard floats each side (pass B row overhang)
#define NBUF 3                    // triple buffer: loads committed 2 iters ahead
#define SMEM_FLOATS (2 * GUARD + NBUF * BUF)    // 18540
#define SMEM_BYTES (SMEM_FLOATS * 4)            // 74160 B -> 3 CTAs/SM
#define CHUNKS_PER_B (HW / PIX)   // 640
#define NCHUNKS (8 * CHUNKS_PER_B)  // 5120
#define L2E 1.4426950408889634f
#define NEGBIG (-1e30f)

__device__ __forceinline__ void cp_async16(unsigned int dst, const float* src) {
    asm volatile("cp.async.cg.shared.global [%0], [%1], 16;" :: "r"(dst), "l"(src) : "memory");
}
__device__ __forceinline__ void cp_commit() {
    asm volatile("cp.async.commit_group;" ::: "memory");
}
template<int N>
__device__ __forceinline__ void cp_wait() {
    asm volatile("cp.async.wait_group %0;" :: "n"(N) : "memory");
}
__device__ __forceinline__ float ex2f(float t) {
    float r;
    asm("ex2.approx.f32 %0, %1;" : "=f"(r) : "f"(t));
    return r;
}

__global__ __launch_bounds__(NT)
void flow_regression_kernel(const float* __restrict__ x, float* __restrict__ out) {
    extern __shared__ float s_raw[];
    float* s0 = s_raw + GUARD;        // buffer i at s0 + i*BUF
    const int tid = threadIdx.x;
    const int bid = blockIdx.x;
    const int G   = gridDim.x;
    const unsigned int sbase0 = (unsigned int)__cvta_generic_to_shared(s0);

    const int sub = tid & 7;          // eighth of per-pixel work
    const int p   = tid >> 3;         // pixel 0..31

    const int plane0 = tid >> 3;      // load mapping: line tid -> plane, q
    const int q0     = (tid & 7) * 4;

    // ---- issue loads for one chunk: 1352 16B lines, incremental addressing ----
    auto issue_load = [&](int g, int nb) {
        int b  = g / CHUNKS_PER_B;
        int ch = g - b * CHUNKS_PER_B;
        const float* gp = x + (size_t)b * (UV * HW) + ch * PIX + plane0 * HW + q0;
        unsigned int dst = sbase0 + (unsigned int)(nb * BUF + plane0 * RS + q0) * 4u;
        #pragma unroll
        for (int k = 0; k < 5; k++) {                 // lines tid + 256k (1280)
            cp_async16(dst, gp);
            gp  += 32 * HW;
            dst += 32 * RS * 4;
        }
        if (tid < 72) cp_async16(dst, gp);            // lines 1280..1351
        cp_commit();
    };

    // prologue: two chunks in flight
    issue_load(bid, 0);
    if (bid + G < NCHUNKS) issue_load(bid + G, 1);
    int nb = 0;

    for (int g = bid; g < NCHUNKS; g += G) {
        if (g + G < NCHUNKS) cp_wait<1>();    // completes chunk g's group (leaves newest)
        else                 cp_wait<0>();    // last chunk: drain everything
        __syncthreads();                      // buf nb visible; reads of buf (nb+2)%3 finished
        if (g + 2 * G < NCHUNKS) issue_load(g + 2 * G, (nb + 2) % NBUF);

        const float* sp = s0 + nb * BUF + p;

        // ---- Pass A: argmax over 169, 8-way split (ascending uv; ties -> lowest uv) ----
        float m  = -CUDART_INF_F;
        int   am = 0;
        {
            const float* r = sp + sub * RS;
            #pragma unroll 7
            for (int t = 0; t < 21; t++) {
                float v = r[t * 8 * RS];
                int uv = sub + 8 * t;
                if (v > m) { m = v; am = uv; }
            }
            if (sub == 0) {
                float v = sp[168 * RS];
                if (v > m) { m = v; am = 168; }
            }
        }
        #pragma unroll
        for (int off = 1; off <= 4; off <<= 1) {
            float mo = __shfl_xor_sync(0xffffffffu, m,  off);
            int   ao = __shfl_xor_sync(0xffffffffu, am, off);
            if (mo > m || (mo == m && ao < am)) { m = mo; am = ao; }
        }
        const int ui = am / VD;
        const int vi = am - ui * VD;
        const float cc = m * L2E;                  // exp(x-m) = ex2(x*L2E - cc)

        // ---- Pass B (row-based): thread owns row du=sub-4; row du=+4 distributed ----
        unsigned int vmV = 0x1FFu;                 // v = vi-4+j valid iff 0<=v<=12
        if (vi < 4) vmV &= (0x1FFu << (4 - vi));
        if (vi > 8) vmV &= (0x1FFu >> (vi - 8));

        const int u   = ui + sub - 4;
        const bool oku = (unsigned)u <= 12u;
        const int uc  = min(max(u, 0), 12);
        const float wu = (float)(u - 6);
        const unsigned int vm = oku ? vmV : 0u;

        float Zb = 0.0f, Zx = 0.0f, T = 0.0f;      // T = sum e*j
        {
            const float* r = sp + (uc * VD + vi - 4) * RS;   // guards absorb overhang
            #pragma unroll
            for (int j = 0; j < 9; j++) {
                float a = (vm & (1u << j)) ? r[j * RS] : NEGBIG;
                float e = ex2f(fmaf(a, L2E, -cc));
                Zb += e;
                T = fmaf(e, (float)j, T);
            }
        }
        const int u4 = ui + 4;
        const bool ok4 = (u4 <= 12);
        const int uc4 = min(u4, 12);
        const float wu4 = (float)(u4 - 6);
        {
            const float* r4 = sp + (uc4 * VD + vi - 4) * RS;
            bool oke = ok4 && ((vmV >> sub) & 1u);
            float a1 = oke ? r4[sub * RS] : NEGBIG;
            float e1 = ex2f(fmaf(a1, L2E, -cc));
            Zx += e1;
            T = fmaf(e1, (float)sub, T);

            bool oke8 = ok4 && (sub == 0) && ((vmV >> 8) & 1u);
            float a2 = oke8 ? r4[8 * RS] : NEGBIG;
            float e2 = ex2f(fmaf(a2, L2E, -cc));
            Zx += e2;
            T = fmaf(e2, 8.0f, T);
        }

        float Z  = Zb + Zx;
        float sU = fmaf(wu, Zb, wu4 * Zx);
        #pragma unroll
        for (int off = 1; off <= 4; off <<= 1) {
            Z  += __shfl_xor_sync(0xffffffffu, Z,  off);
            sU += __shfl_xor_sync(0xffffffffu, sU, off);
            T  += __shfl_xor_sync(0xffffffffu, T,  off);
        }

        if (sub == 0) {
            const int b  = g / CHUNKS_PER_B;
            const int ch = g - b * CHUNKS_PER_B;
            const float inv = __frcp_rn(Z);
            const float sV = fmaf((float)(vi - 10), Z, T);   // wv = (vi-10)+j
            const int pix = ch * PIX + p;
            out[(b * 2 + 0) * HW + pix] = sU * inv;
            out[(b * 2 + 1) * HW + pix] = sV * inv;
        }
        nb = (nb + 1) % NBUF;
        // next iteration's __syncthreads orders these reads before that buffer's refill
    }
}

extern "C" void kernel_launch(void* const* d_in, const int* in_sizes, int n_in,
                              void* d_out, int out_size) {
    (void)in_sizes; (void)n_in; (void)out_size;
    const float* x = (const float*)d_in[0];
    float* out = (float*)d_out;

    static int nsm = 0;
    if (nsm == 0) {
        cudaDeviceGetAttribute(&nsm, cudaDevAttrMultiProcessorCount, 0);
        if (nsm <= 0) nsm = 148;
        cudaFuncSetAttribute(flow_regression_kernel,
                             cudaFuncAttributeMaxDynamicSharedMemorySize, SMEM_BYTES);
        cudaFuncSetAttribute(flow_regression_kernel,
                             cudaFuncAttributePreferredSharedMemoryCarveout, 100);
    }

    const int nblocks = 3 * nsm;      // persistent: 3 CTAs per SM, depth-2 pipeline
    flow_regression_kernel<<<nblocks, NT, SMEM_BYTES>>>(x, out);
}